// round 1
// baseline (speedup 1.0000x reference)
#include <cuda_runtime.h>
#include <math.h>

#define Tt 32
#define Cc 180
#define Hh 6
#define HDd 30
#define Ff 720
#define NT 256
#define EPS 1e-5f

// smem layout (floats):
// xs  [32*180]             x, later x2 (post-attn residual)
// hs  [32*180]             LN1 output, later LN2 output
// qs  [6*32*30]  \
// ks  [6*32*30]   |  union with hid[32*720] (MLP hidden) after attention
// vs  [6*32*30]   |
// ss  [6*32*32]  /
#define SM_X   0
#define SM_H   (Tt*Cc)
#define SM_Q   (2*Tt*Cc)
#define SM_K   (SM_Q + Hh*Tt*HDd)
#define SM_V   (SM_K + Hh*Tt*HDd)
#define SM_S   (SM_V + Hh*Tt*HDd)
#define SM_HID SM_Q
#define SM_TOTAL (SM_S + Hh*Tt*Tt)   // 34944 floats = 139776 B

__global__ void __launch_bounds__(NT, 1) block_kernel(
    const float* __restrict__ x,
    const float* __restrict__ wq, const float* __restrict__ wk, const float* __restrict__ wv,
    const float* __restrict__ g1, const float* __restrict__ be1,
    const float* __restrict__ g2, const float* __restrict__ be2,
    const float* __restrict__ w1, const float* __restrict__ b1,
    const float* __restrict__ w2, const float* __restrict__ b2,
    float* __restrict__ out)
{
    extern __shared__ float sm[];
    float* xs = sm + SM_X;
    float* hs = sm + SM_H;
    float* qs = sm + SM_Q;
    float* ks = sm + SM_K;
    float* vs = sm + SM_V;
    float* ss = sm + SM_S;
    float* hid = sm + SM_HID;

    const int b   = blockIdx.x;
    const int tid = threadIdx.x;
    const int w   = tid >> 5;
    const int ln  = tid & 31;
    const float* xg = x + (size_t)b * (Tt*Cc);

    // ---- load x (float4 coalesced) ----
    {
        const float4* xg4 = reinterpret_cast<const float4*>(xg);
        float4* xs4 = reinterpret_cast<float4*>(xs);
        for (int i = tid; i < (Tt*Cc)/4; i += NT) xs4[i] = xg4[i];
    }
    __syncthreads();

    // ---- LN1: per-row warp reduction ----
    for (int t = w; t < Tt; t += 8) {
        float s = 0.f, s2 = 0.f;
        for (int c = ln; c < Cc; c += 32) { float v = xs[t*Cc+c]; s += v; s2 += v*v; }
        #pragma unroll
        for (int o = 16; o; o >>= 1) {
            s  += __shfl_xor_sync(0xffffffffu, s,  o);
            s2 += __shfl_xor_sync(0xffffffffu, s2, o);
        }
        float mu = s * (1.f/Cc);
        float inv = rsqrtf(s2 * (1.f/Cc) - mu*mu + EPS);
        for (int c = ln; c < Cc; c += 32)
            hs[t*Cc+c] = (xs[t*Cc+c] - mu) * inv * g1[c] + be1[c];
    }
    __syncthreads();

    // ---- QKV: 540 jobs, each = one output column (head h, dim d) x all 32 t ----
    for (int job = tid; job < 3*Cc; job += NT) {
        int mat = job / Cc;
        int n   = job % Cc;
        int hh  = n / HDd, d = n % HDd;
        const float* W = (mat == 0 ? wq : (mat == 1 ? wk : wv)) + hh*(Cc*HDd) + d;
        float a[Tt];
        #pragma unroll
        for (int i = 0; i < Tt; i++) a[i] = 0.f;
        #pragma unroll 4
        for (int c = 0; c < Cc; c++) {
            float wv_ = __ldg(W + c*HDd);
            #pragma unroll
            for (int i = 0; i < Tt; i++) a[i] += hs[i*Cc + c] * wv_;
        }
        float* dst = (mat == 0 ? qs : (mat == 1 ? ks : vs)) + hh*(Tt*HDd) + d;
        #pragma unroll
        for (int i = 0; i < Tt; i++) dst[i*HDd] = a[i];
    }
    __syncthreads();

    // ---- scores + causal softmax: one warp per (h, ti) row, lane = tj ----
    for (int row = w; row < Hh*Tt; row += 8) {
        int hh = row / Tt, ti = row % Tt;
        const float* qp = qs + hh*(Tt*HDd) + ti*HDd;
        const float* kp = ks + hh*(Tt*HDd) + ln*HDd;
        float dot = 0.f;
        #pragma unroll
        for (int d = 0; d < HDd; d++) dot += qp[d] * kp[d];
        dot *= 0.1825741858f;  // 30^-0.5
        float val = (ln <= ti) ? dot : -1e30f;
        float m = val;
        #pragma unroll
        for (int o = 16; o; o >>= 1) m = fmaxf(m, __shfl_xor_sync(0xffffffffu, m, o));
        float e = (ln <= ti) ? __expf(val - m) : 0.f;
        float sum = e;
        #pragma unroll
        for (int o = 16; o; o >>= 1) sum += __shfl_xor_sync(0xffffffffu, sum, o);
        ss[hh*(Tt*Tt) + ti*Tt + ln] = e / sum;
    }
    __syncthreads();

    // ---- attn @ V + residual into xs: 360 jobs (col n, t-tile 16) ----
    for (int job = tid; job < 2*Cc; job += NT) {
        int tg = job / Cc, n = job % Cc;
        int hh = n / HDd, d = n % HDd;
        int t0 = tg * 16;
        const float* vp = vs + hh*(Tt*HDd) + d;
        const float* sp = ss + hh*(Tt*Tt) + t0*Tt;
        float a[16];
        #pragma unroll
        for (int i = 0; i < 16; i++) a[i] = 0.f;
        #pragma unroll 4
        for (int tj = 0; tj < Tt; tj++) {
            float vv = vp[tj*HDd];
            #pragma unroll
            for (int i = 0; i < 16; i++) a[i] += sp[i*Tt + tj] * vv;
        }
        #pragma unroll
        for (int i = 0; i < 16; i++) xs[(t0+i)*Cc + n] += a[i];
    }
    __syncthreads();

    // ---- LN2: xs (= x2) -> hs ----
    for (int t = w; t < Tt; t += 8) {
        float s = 0.f, s2 = 0.f;
        for (int c = ln; c < Cc; c += 32) { float v = xs[t*Cc+c]; s += v; s2 += v*v; }
        #pragma unroll
        for (int o = 16; o; o >>= 1) {
            s  += __shfl_xor_sync(0xffffffffu, s,  o);
            s2 += __shfl_xor_sync(0xffffffffu, s2, o);
        }
        float mu = s * (1.f/Cc);
        float inv = rsqrtf(s2 * (1.f/Cc) - mu*mu + EPS);
        for (int c = ln; c < Cc; c += 32)
            hs[t*Cc+c] = (xs[t*Cc+c] - mu) * inv * g2[c] + be2[c];
    }
    __syncthreads();

    // ---- MLP GEMM1: hid[t][f] = relu(hs @ w1 + b1), 720 jobs x 32 t ----
    for (int f = tid; f < Ff; f += NT) {
        float a[Tt];
        float bb = b1[f];
        #pragma unroll
        for (int i = 0; i < Tt; i++) a[i] = bb;
        const float* W = w1 + f;
        #pragma unroll 4
        for (int c = 0; c < Cc; c++) {
            float wv_ = __ldg(W + c*Ff);
            #pragma unroll
            for (int i = 0; i < Tt; i++) a[i] += hs[i*Cc + c] * wv_;
        }
        #pragma unroll
        for (int i = 0; i < Tt; i++) hid[i*Ff + f] = fmaxf(a[i], 0.f);
    }
    __syncthreads();

    // ---- MLP GEMM2 + residual -> global out: 360 jobs (col n, t-tile 16) ----
    float* og = out + (size_t)b * (Tt*Cc);
    for (int job = tid; job < 2*Cc; job += NT) {
        int tg = job / Cc, n = job % Cc;
        int t0 = tg * 16;
        const float* W = w2 + n;
        float a[16];
        #pragma unroll
        for (int i = 0; i < 16; i++) a[i] = 0.f;
        #pragma unroll 4
        for (int cc = 0; cc < Ff; cc++) {
            float wv_ = __ldg(W + cc*Cc);
            #pragma unroll
            for (int i = 0; i < 16; i++) a[i] += hid[(t0+i)*Ff + cc] * wv_;
        }
        float bb = b2[n];
        #pragma unroll
        for (int i = 0; i < 16; i++)
            og[(t0+i)*Cc + n] = xs[(t0+i)*Cc + n] + bb + a[i];
    }
}

extern "C" void kernel_launch(void* const* d_in, const int* in_sizes, int n_in,
                              void* d_out, int out_size) {
    const float* x   = (const float*)d_in[0];
    const float* wq  = (const float*)d_in[1];
    const float* wk  = (const float*)d_in[2];
    const float* wv  = (const float*)d_in[3];
    const float* g1  = (const float*)d_in[4];
    const float* be1 = (const float*)d_in[5];
    const float* g2  = (const float*)d_in[6];
    const float* be2 = (const float*)d_in[7];
    const float* w1  = (const float*)d_in[8];
    const float* b1  = (const float*)d_in[9];
    const float* w2  = (const float*)d_in[10];
    const float* b2  = (const float*)d_in[11];
    float* out = (float*)d_out;

    const int smem_bytes = SM_TOTAL * sizeof(float);
    cudaFuncSetAttribute(block_kernel, cudaFuncAttributeMaxDynamicSharedMemorySize, smem_bytes);
    block_kernel<<<4096, NT, smem_bytes>>>(x, wq, wk, wv, g1, be1, g2, be2, w1, b1, w2, b2, out);
}